// round 14
// baseline (speedup 1.0000x reference)
#include <cuda_runtime.h>
#include <cuda_fp16.h>
#include <cstdint>

// ---------------------------------------------------------------------------
// TransformerBlock: B=256, T=256, C=384, H=6, D=64, F=1536, N=B*T=65536
// fp16 mma.sync (fp32 accum), cp.async pipelines, ldmatrix frags.
// GEMM: BM=256 BN=128, warp 64x64 -> smem crossbar under 128 B/cyc.
// ---------------------------------------------------------------------------

#define NTOK  65536
#define CDIM  384
#define NHEAD 6
#define HDIM  64
#define FDIM  1536
#define TLEN  256
#define QKVC  1152

__device__ __half g_h   [(size_t)NTOK * CDIM];
__device__ __half g_qkv [(size_t)NTOK * QKVC];
__device__ __half g_attn[(size_t)NTOK * CDIM];
__device__ float  g_xmid[(size_t)NTOK * CDIM];
__device__ __half g_ff  [(size_t)NTOK * FDIM];
__device__ __half g_wqkv[(size_t)QKVC * CDIM];
__device__ __half g_wp  [(size_t)CDIM * CDIM];
__device__ __half g_w1  [(size_t)FDIM * CDIM];
__device__ __half g_w2  [(size_t)CDIM * FDIM];

// ---------------------------------------------------------------------------
// helpers
// ---------------------------------------------------------------------------
__device__ __forceinline__ float fast_exp_scaled(float dot) {
    float y = dot * 0.1803368801111244f;           // 0.125 * log2(e)
    float r = y + 12582912.0f;
    float nf = r - 12582912.0f;
    float f = y - nf;
    float p = 1.3333558146e-3f;
    p = fmaf(p, f, 9.6181291076e-3f);
    p = fmaf(p, f, 5.5504108664e-2f);
    p = fmaf(p, f, 2.4022650696e-1f);
    p = fmaf(p, f, 6.9314718056e-1f);
    p = fmaf(p, f, 1.0f);
    int ni = __float_as_int(r) - 0x4B400000;
    return __int_as_float(__float_as_int(p) + (ni << 23));
}

#define MMA16(c, a, b)                                                          \
    asm volatile("mma.sync.aligned.m16n8k16.row.col.f32.f16.f16.f32 "          \
                 "{%0,%1,%2,%3}, {%4,%5,%6,%7}, {%8,%9}, {%0,%1,%2,%3};"       \
                 : "+f"((c)[0]), "+f"((c)[1]), "+f"((c)[2]), "+f"((c)[3])      \
                 : "r"((a)[0]), "r"((a)[1]), "r"((a)[2]), "r"((a)[3]),         \
                   "r"((b)[0]), "r"((b)[1]))

__device__ __forceinline__ void cp16(uint32_t dst, const void* src) {
    asm volatile("cp.async.cg.shared.global [%0], [%1], 16;" :: "r"(dst), "l"(src));
}
#define CP_COMMIT() asm volatile("cp.async.commit_group;")
#define CP_WAIT1()  asm volatile("cp.async.wait_group 1;")
#define CP_WAIT2()  asm volatile("cp.async.wait_group 2;")

__device__ __forceinline__ void ldsm4(uint32_t* r, uint32_t addr) {
    asm volatile("ldmatrix.sync.aligned.m8n8.x4.shared.b16 {%0,%1,%2,%3}, [%4];"
                 : "=r"(r[0]), "=r"(r[1]), "=r"(r[2]), "=r"(r[3]) : "r"(addr));
}
__device__ __forceinline__ void ldsm4t(uint32_t* r, uint32_t addr) {
    asm volatile("ldmatrix.sync.aligned.m8n8.x4.trans.shared.b16 {%0,%1,%2,%3}, [%4];"
                 : "=r"(r[0]), "=r"(r[1]), "=r"(r[2]), "=r"(r[3]) : "r"(addr));
}
__device__ __forceinline__ uint32_t scvta(const void* p) {
    return (uint32_t)__cvta_generic_to_shared(p);
}

// ---------------------------------------------------------------------------
// fp16 GEMM: C[M,Nall] = A[M,K] @ Bt[Nall,K]^T, fp32 accum.
// BM=256, BN=128, BK=32. 256 thr = 8 warps (4m x 2n), warp tile 64x64.
// 4-stage cp.async pipeline (sound tail), ldmatrix frags, 1 CTA/SM.
// ---------------------------------------------------------------------------
#define A_STG 10240            // halves per A stage (256*40)
#define B_STG 5120             // halves per B stage (128*40)
#define GEMM_SMEM ((4 * (A_STG + B_STG)) * 2)   // 122880 B

template<bool OUTH, bool HB, bool RELU, bool RESID>
__global__ void __launch_bounds__(256, 1) gemm_h(const __half* __restrict__ A,
                                                 const __half* __restrict__ Bt,
                                                 const float* __restrict__ bias,
                                                 const float* __restrict__ resid,
                                                 void* __restrict__ Cout,
                                                 int K, int Nall)
{
    extern __shared__ __half sh[];
    __half* As = sh;                    // [4][256*40]
    __half* Bs = sh + 4 * A_STG;        // [4][128*40]
    uint32_t aBase = scvta(As), bBase = scvta(Bs);

    int tid = threadIdx.x, lane = tid & 31, warp = tid >> 5;
    int wm = warp >> 1, wn = warp & 1;
    size_t m0 = (size_t)blockIdx.y * 256;
    int n0 = blockIdx.x * 128;
    const int NT = K >> 5;

    float acc[4][8][4] = {};

    int lrow = tid >> 2, lkc = tid & 3;
    const __half* Ag = A + (m0 + lrow) * (size_t)K + lkc * 8;
    const __half* Bg = Bt + (size_t)(n0 + lrow) * K + lkc * 8;
    uint32_t sOff = (uint32_t)(lrow * 40 + lkc * 8) * 2;

    auto issue = [&](int kt) {
        int st = kt & 3;
        int k0 = kt * 32;
        uint32_t d = aBase + st * (A_STG * 2) + sOff;
#pragma unroll
        for (int i = 0; i < 4; i++)
            cp16(d + i * (64 * 80), Ag + (size_t)(i * 64) * K + k0);
        d = bBase + st * (B_STG * 2) + sOff;
#pragma unroll
        for (int i = 0; i < 2; i++)
            cp16(d + i * (64 * 80), Bg + (size_t)(i * 64) * K + k0);
        CP_COMMIT();
    };

    uint32_t aFrag = aBase + (uint32_t)(((wm * 64 + (lane & 15)) * 40 + (lane >> 4) * 8) * 2);
    uint32_t bFrag = bBase + (uint32_t)(((wn * 64 + ((lane >> 4) & 1) * 8 + (lane & 7)) * 40
                                         + ((lane >> 3) & 1) * 8) * 2);

    auto compute = [&](int st) {
        uint32_t aso = (uint32_t)(st * (A_STG * 2));
        uint32_t bso = (uint32_t)(st * (B_STG * 2));
#pragma unroll
        for (int ks = 0; ks < 2; ks++) {
            uint32_t ko = ks * 32;
            uint32_t a[4][4], bfr[4][4];
#pragma unroll
            for (int mi = 0; mi < 4; mi++) ldsm4(a[mi], aFrag + aso + ko + mi * 1280);
#pragma unroll
            for (int nh = 0; nh < 4; nh++) ldsm4(bfr[nh], bFrag + bso + ko + nh * 1280);
#pragma unroll
            for (int mi = 0; mi < 4; mi++)
#pragma unroll
                for (int ni = 0; ni < 8; ni++)
                    MMA16(acc[mi][ni], a[mi], &bfr[ni >> 1][(ni & 1) * 2]);
        }
    };

    issue(0);
    issue(1);
    issue(2);
    for (int kt = 0; kt < NT; kt++) {
        CP_WAIT2();            // chunks 0..kt complete
        __syncthreads();
        if (kt + 3 < NT) issue(kt + 3);
        else CP_COMMIT();      // keep group-count invariant through the tail
        compute(kt & 3);
    }

    // ---- epilogue ----
#pragma unroll
    for (int mi = 0; mi < 4; mi++)
#pragma unroll
        for (int ni = 0; ni < 8; ni++) {
            int col = n0 + wn * 64 + ni * 8 + 2 * (lane & 3);
            float bx = 0.f, by = 0.f;
            if (HB) { bx = bias[col]; by = bias[col + 1]; }
#pragma unroll
            for (int rh = 0; rh < 2; rh++) {
                size_t row = m0 + wm * 64 + mi * 16 + (lane >> 2) + rh * 8;
                float v0 = acc[mi][ni][rh * 2 + 0] + bx;
                float v1 = acc[mi][ni][rh * 2 + 1] + by;
                if (RELU) { v0 = fmaxf(v0, 0.f); v1 = fmaxf(v1, 0.f); }
                if (RESID) {
                    const float2 rv = *(const float2*)(resid + row * (size_t)Nall + col);
                    v0 += rv.x; v1 += rv.y;
                }
                if (OUTH) {
                    *(__half2*)((__half*)Cout + row * (size_t)Nall + col) =
                        __floats2half2_rn(v0, v1);
                } else {
                    *(float2*)((float*)Cout + row * (size_t)Nall + col) = make_float2(v0, v1);
                }
            }
        }
}

// ---------------------------------------------------------------------------
// merged weight prep: pack QKV + transpose Wp/W1/W2 to half [n][k]
// ---------------------------------------------------------------------------
#define PK_QKV   442368
#define PK_WP    147456
#define PK_W1    589824
#define PK_TOT   (PK_QKV + PK_WP + PK_W1 + PK_W1)

__global__ void prep_w(const float* __restrict__ Wq, const float* __restrict__ Wk,
                       const float* __restrict__ Wv, const float* __restrict__ Wp,
                       const float* __restrict__ W1, const float* __restrict__ W2,
                       __half* __restrict__ owqkv, __half* __restrict__ owp,
                       __half* __restrict__ ow1, __half* __restrict__ ow2)
{
    int idx = blockIdx.x * 256 + threadIdx.x;
    if (idx < PK_QKV) {
        int mat = idx / 147456;
        int r = idx - mat * 147456;
        int h = r / 24576;
        int r2 = r - h * 24576;
        int c = r2 >> 6;
        int d = r2 & 63;
        const float* W = (mat == 0) ? Wq : (mat == 1) ? Wk : Wv;
        owqkv[(size_t)(mat * CDIM + h * HDIM + d) * CDIM + c] = __float2half(W[r]);
        return;
    }
    idx -= PK_QKV;
    if (idx < PK_WP) {
        int k = idx / CDIM, n = idx - k * CDIM;
        owp[(size_t)n * CDIM + k] = __float2half(Wp[idx]);
        return;
    }
    idx -= PK_WP;
    if (idx < PK_W1) {
        int k = idx / FDIM, n = idx - k * FDIM;
        ow1[(size_t)n * CDIM + k] = __float2half(W1[idx]);
        return;
    }
    idx -= PK_W1;
    {
        int k = idx / CDIM, n = idx - k * CDIM;
        ow2[(size_t)n * FDIM + k] = __float2half(W2[idx]);
    }
}

// ---------------------------------------------------------------------------
// LayerNorm: one warp per token, shfl-only reductions, no barriers.
// ---------------------------------------------------------------------------
__global__ void __launch_bounds__(256) ln_kernel(const float* __restrict__ x,
                                                 const float* __restrict__ g,
                                                 const float* __restrict__ be,
                                                 __half* __restrict__ out)
{
    int lane = threadIdx.x & 31;
    size_t token = (size_t)blockIdx.x * 8 + (threadIdx.x >> 5);
    const float* xr = x + token * CDIM;

    float4 v[3];
#pragma unroll
    for (int p = 0; p < 3; p++) v[p] = *(const float4*)(xr + lane * 4 + p * 128);

    float s = 0.f;
#pragma unroll
    for (int p = 0; p < 3; p++) s += (v[p].x + v[p].y) + (v[p].z + v[p].w);
#pragma unroll
    for (int o = 16; o; o >>= 1) s += __shfl_xor_sync(0xFFFFFFFFu, s, o);
    float mu = s * (1.0f / 384.0f);

    float ss = 0.f;
#pragma unroll
    for (int p = 0; p < 3; p++) {
        float a0 = v[p].x - mu, a1 = v[p].y - mu, a2 = v[p].z - mu, a3 = v[p].w - mu;
        ss += (a0 * a0 + a1 * a1) + (a2 * a2 + a3 * a3);
    }
#pragma unroll
    for (int o = 16; o; o >>= 1) ss += __shfl_xor_sync(0xFFFFFFFFu, ss, o);
    float rstd = rsqrtf(ss * (1.0f / 384.0f) + 1e-5f);

    __half* orow = out + token * CDIM;
#pragma unroll
    for (int p = 0; p < 3; p++) {
        int c = lane * 4 + p * 128;
        float4 gv = *(const float4*)(g + c);
        float4 bv = *(const float4*)(be + c);
        __half2 h0 = __floats2half2_rn((v[p].x - mu) * rstd * gv.x + bv.x,
                                       (v[p].y - mu) * rstd * gv.y + bv.y);
        __half2 h1 = __floats2half2_rn((v[p].z - mu) * rstd * gv.z + bv.z,
                                       (v[p].w - mu) * rstd * gv.w + bv.w);
        uint2 pk = make_uint2(*(uint32_t*)&h0, *(uint32_t*)&h1);
        *(uint2*)(orow + c) = pk;
    }
}

// ---------------------------------------------------------------------------
// Flash attention, fp16 mma + ldmatrix, cp.async double-buffered K/V.
// Grid (2, 1536), 256 thr = 8 warps (4m x 2n). P via smem.
// ---------------------------------------------------------------------------
#define ATT_SMEM 74752

__global__ void __launch_bounds__(256) attn_mma(const __half* __restrict__ qkv,
                                                __half* __restrict__ Og)
{
    extern __shared__ __half sma[];
    __half* Qs = sma;                    // 9216
    __half* Ks = Qs + 9216;              // 2 * 4608
    __half* Vs = Ks + 9216;              // 2 * 4608
    __half* Ps = Vs + 9216;              // 9216
    float* lsum = (float*)(Ps + 9216);   // 256 floats

    uint32_t qB = scvta(Qs), kB = scvta(Ks), vB = scvta(Vs), pB = scvta(Ps);

    int qt = blockIdx.x;
    int bh = blockIdx.y;
    int b = bh / NHEAD, h = bh % NHEAD;
    int tid = threadIdx.x, lane = tid & 31, warp = tid >> 5;
    int wm = warp >> 1, wn = warp & 1;
    int lr = lane >> 2;

    size_t tokbase = (size_t)b * TLEN;
    const __half* Kg = qkv + tokbase * QKVC + CDIM + h * HDIM;
    const __half* Vg = qkv + tokbase * QKVC + 2 * CDIM + h * HDIM;

    int qrow[4], qc8[4];
#pragma unroll
    for (int i = 0; i < 4; i++) { int f = tid + i * 256; qrow[i] = f >> 3; qc8[i] = f & 7; }
    int krow0 = tid >> 3, kc8 = tid & 7;

    auto prefetch_kv = [&](int ci) {
        uint32_t buf = (uint32_t)((ci & 1) * 4608 * 2);
        int srow0 = ci * 64;
#pragma unroll
        for (int i = 0; i < 2; i++) {
            int srow = krow0 + i * 32;
            uint32_t off = (uint32_t)((srow * 72 + kc8 * 8) * 2);
            cp16(kB + buf + off, Kg + (size_t)(srow0 + srow) * QKVC + kc8 * 8);
            cp16(vB + buf + off, Vg + (size_t)(srow0 + srow) * QKVC + kc8 * 8);
        }
    };

#pragma unroll
    for (int i = 0; i < 4; i++) {
        cp16(qB + (uint32_t)((qrow[i] * 72 + qc8[i] * 8) * 2),
             qkv + (tokbase + qt * 128 + qrow[i]) * QKVC + h * HDIM + qc8[i] * 8);
    }
    prefetch_kv(0);
    CP_COMMIT();

    float o[2][4][4] = {};
    float lacc[2][2] = {};

    uint32_t aOff = (uint32_t)(((wm * 32 + (lane & 15)) * 72 + (lane >> 4) * 8) * 2);
    uint32_t bOffK = (uint32_t)(((wn * 32 + ((lane >> 4) & 1) * 8 + (lane & 7)) * 72
                                 + ((lane >> 3) & 1) * 8) * 2);
    uint32_t bOffV = (uint32_t)(((((lane >> 3) & 1) * 8 + (lane & 7)) * 72
                                 + wn * 32 + ((lane >> 4) & 1) * 8) * 2);

    int nchunk = 2 * (qt + 1);
    for (int ci = 0; ci < nchunk; ci++) {
        int s0 = ci * 64;
        uint32_t kbuf = kB + (uint32_t)((ci & 1) * 9216);
        uint32_t vbuf = vB + (uint32_t)((ci & 1) * 9216);

        __syncthreads();
        if (ci + 1 < nchunk) { prefetch_kv(ci + 1); CP_COMMIT(); }
        else CP_COMMIT();
        CP_WAIT1();
        __syncthreads();

        // S = Q @ K^T
        float s[2][4][4] = {};
#pragma unroll
        for (int ks = 0; ks < 4; ks++) {
            uint32_t ko = ks * 32;
            uint32_t a[2][4], bfr[2][4];
#pragma unroll
            for (int mi = 0; mi < 2; mi++) ldsm4(a[mi], qB + aOff + ko + mi * 2304);
#pragma unroll
            for (int nh = 0; nh < 2; nh++) ldsm4(bfr[nh], kbuf + bOffK + ko + nh * 2304);
#pragma unroll
            for (int mi = 0; mi < 2; mi++)
#pragma unroll
                for (int ni = 0; ni < 4; ni++)
                    MMA16(s[mi][ni], a[mi], &bfr[ni >> 1][(ni & 1) * 2]);
        }

        // mask + exp + row sums + store P
        bool domask = (s0 + 63 > qt * 128);
#pragma unroll
        for (int mi = 0; mi < 2; mi++) {
            int row0 = qt * 128 + wm * 32 + mi * 16 + lr;
            int prow = wm * 32 + mi * 16 + lr;
#pragma unroll
            for (int ni = 0; ni < 4; ni++) {
                int col0 = s0 + wn * 32 + ni * 8 + 2 * (lane & 3);
#pragma unroll
                for (int e = 0; e < 4; e++) {
                    int rr = row0 + (e >> 1) * 8;
                    int cc = col0 + (e & 1);
                    float p = (domask && cc > rr) ? 0.f : fast_exp_scaled(s[mi][ni][e]);
                    s[mi][ni][e] = p;
                    lacc[mi][e >> 1] += p;
                }
                int pcol = wn * 32 + ni * 8 + 2 * (lane & 3);
                *(__half2*)(Ps + prow * 72 + pcol) =
                    __floats2half2_rn(s[mi][ni][0], s[mi][ni][1]);
                *(__half2*)(Ps + (prow + 8) * 72 + pcol) =
                    __floats2half2_rn(s[mi][ni][2], s[mi][ni][3]);
            }
        }
        __syncthreads();

        // O += P @ V
#pragma unroll
        for (int ks = 0; ks < 4; ks++) {
            uint32_t a[2][4], bfr[2][4];
#pragma unroll
            for (int mi = 0; mi < 2; mi++) ldsm4(a[mi], pB + aOff + ks * 32 + mi * 2304);
#pragma unroll
            for (int nh = 0; nh < 2; nh++)
                ldsm4t(bfr[nh], vbuf + bOffV + ks * 2304 + nh * 32);
#pragma unroll
            for (int mi = 0; mi < 2; mi++)
#pragma unroll
                for (int ni = 0; ni < 4; ni++)
                    MMA16(o[mi][ni], a[mi], &bfr[ni >> 1][(ni & 1) * 2]);
        }
    }

    // reduce row sums, publish, combine
#pragma unroll
    for (int mi = 0; mi < 2; mi++)
#pragma unroll
        for (int e = 0; e < 2; e++) {
            lacc[mi][e] += __shfl_xor_sync(0xFFFFFFFFu, lacc[mi][e], 1);
            lacc[mi][e] += __shfl_xor_sync(0xFFFFFFFFu, lacc[mi][e], 2);
        }
    if ((lane & 3) == 0) {
#pragma unroll
        for (int mi = 0; mi < 2; mi++) {
            lsum[wn * 128 + wm * 32 + mi * 16 + lr] = lacc[mi][0];
            lsum[wn * 128 + wm * 32 + mi * 16 + lr + 8] = lacc[mi][1];
        }
    }
    __syncthreads();

    // normalize + store (half)
#pragma unroll
    for (int mi = 0; mi < 2; mi++) {
        int prow = wm * 32 + mi * 16 + lr;
        float inv0 = 1.f / (lsum[prow] + lsum[128 + prow]);
        float inv1 = 1.f / (lsum[prow + 8] + lsum[128 + prow + 8]);
        size_t grow = tokbase + qt * 128 + prow;
#pragma unroll
        for (int ni = 0; ni < 4; ni++) {
            int col = h * HDIM + wn * 32 + ni * 8 + 2 * (lane & 3);
            *(__half2*)(Og + grow * CDIM + col) =
                __floats2half2_rn(o[mi][ni][0] * inv0, o[mi][ni][1] * inv0);
            *(__half2*)(Og + (grow + 8) * CDIM + col) =
                __floats2half2_rn(o[mi][ni][2] * inv1, o[mi][ni][3] * inv1);
        }
    }
}

// ---------------------------------------------------------------------------
// Host launch
// ---------------------------------------------------------------------------
extern "C" void kernel_launch(void* const* d_in, const int* in_sizes, int n_in,
                              void* d_out, int out_size)
{
    const float* x   = (const float*)d_in[0];
    const float* Wq  = (const float*)d_in[1];
    const float* Wk  = (const float*)d_in[2];
    const float* Wv  = (const float*)d_in[3];
    const float* Wp  = (const float*)d_in[4];
    const float* bp  = (const float*)d_in[5];
    const float* W1  = (const float*)d_in[6];
    const float* b1  = (const float*)d_in[7];
    const float* W2  = (const float*)d_in[8];
    const float* b2  = (const float*)d_in[9];
    const float* g1  = (const float*)d_in[10];
    const float* be1 = (const float*)d_in[11];
    const float* g2  = (const float*)d_in[12];
    const float* be2 = (const float*)d_in[13];
    float* out = (float*)d_out;

    __half *h, *qkv, *attn, *ff, *wqkv, *wp, *w1, *w2;
    float *xmid;
    cudaGetSymbolAddress((void**)&h,    g_h);
    cudaGetSymbolAddress((void**)&qkv,  g_qkv);
    cudaGetSymbolAddress((void**)&attn, g_attn);
    cudaGetSymbolAddress((void**)&xmid, g_xmid);
    cudaGetSymbolAddress((void**)&ff,   g_ff);
    cudaGetSymbolAddress((void**)&wqkv, g_wqkv);
    cudaGetSymbolAddress((void**)&wp,   g_wp);
    cudaGetSymbolAddress((void**)&w1,   g_w1);
    cudaGetSymbolAddress((void**)&w2,   g_w2);

    cudaFuncSetAttribute(gemm_h<true, false, false, false>,
                         cudaFuncAttributeMaxDynamicSharedMemorySize, GEMM_SMEM);
    cudaFuncSetAttribute(gemm_h<false, true, false, true>,
                         cudaFuncAttributeMaxDynamicSharedMemorySize, GEMM_SMEM);
    cudaFuncSetAttribute(gemm_h<true, true, true, false>,
                         cudaFuncAttributeMaxDynamicSharedMemorySize, GEMM_SMEM);
    cudaFuncSetAttribute(attn_mma, cudaFuncAttributeMaxDynamicSharedMemorySize, ATT_SMEM);

    // 0. merged weight prep
    prep_w<<<(PK_TOT + 255) / 256, 256>>>(Wq, Wk, Wv, Wp, W1, W2, wqkv, wp, w1, w2);
    // 1. LN1 -> h (half)
    ln_kernel<<<NTOK / 8, 256>>>(x, g1, be1, h);
    // 2. QKV GEMM -> qkv (half)
    gemm_h<true, false, false, false><<<dim3(QKVC / 128, NTOK / 256), 256, GEMM_SMEM>>>(
        h, wqkv, nullptr, nullptr, qkv, CDIM, QKVC);
    // 3. flash attention -> attn (half)
    attn_mma<<<dim3(2, TLEN * NHEAD), 256, ATT_SMEM>>>(qkv, attn);
    // 4. proj + bias + residual(x) -> xmid (fp32)
    gemm_h<false, true, false, true><<<dim3(CDIM / 128, NTOK / 256), 256, GEMM_SMEM>>>(
        attn, wp, bp, x, xmid, CDIM, CDIM);
    // 5. LN2 -> h (half)
    ln_kernel<<<NTOK / 8, 256>>>(xmid, g2, be2, h);
    // 6. FF1 + bias + relu -> ff (half)
    gemm_h<true, true, true, false><<<dim3(FDIM / 128, NTOK / 256), 256, GEMM_SMEM>>>(
        h, w1, b1, nullptr, ff, CDIM, FDIM);
    // 7. FF2 + bias + residual(xmid) -> out (fp32)
    gemm_h<false, true, false, true><<<dim3(CDIM / 128, NTOK / 256), 256, GEMM_SMEM>>>(
        ff, w2, b2, xmid, out, FDIM, CDIM);
}

// round 15
// speedup vs baseline: 1.0974x; 1.0974x over previous
#include <cuda_runtime.h>
#include <cuda_fp16.h>
#include <cstdint>

// ---------------------------------------------------------------------------
// TransformerBlock: B=256, T=256, C=384, H=6, D=64, F=1536, N=B*T=65536
// fp16 mma.sync (fp32 accum), cp.async pipelines, ldmatrix frags.
// GEMM: BM=128 BN=128 (proven R11 tiling), 5-stage cp.async pipeline.
// ---------------------------------------------------------------------------

#define NTOK  65536
#define CDIM  384
#define NHEAD 6
#define HDIM  64
#define FDIM  1536
#define TLEN  256
#define QKVC  1152

__device__ __half g_h   [(size_t)NTOK * CDIM];
__device__ __half g_qkv [(size_t)NTOK * QKVC];
__device__ __half g_attn[(size_t)NTOK * CDIM];
__device__ float  g_xmid[(size_t)NTOK * CDIM];
__device__ __half g_ff  [(size_t)NTOK * FDIM];
__device__ __half g_wqkv[(size_t)QKVC * CDIM];
__device__ __half g_wp  [(size_t)CDIM * CDIM];
__device__ __half g_w1  [(size_t)FDIM * CDIM];
__device__ __half g_w2  [(size_t)CDIM * FDIM];

// ---------------------------------------------------------------------------
// helpers
// ---------------------------------------------------------------------------
__device__ __forceinline__ float fast_exp_scaled(float dot) {
    float y = dot * 0.1803368801111244f;           // 0.125 * log2(e)
    float r = y + 12582912.0f;
    float nf = r - 12582912.0f;
    float f = y - nf;
    float p = 1.3333558146e-3f;
    p = fmaf(p, f, 9.6181291076e-3f);
    p = fmaf(p, f, 5.5504108664e-2f);
    p = fmaf(p, f, 2.4022650696e-1f);
    p = fmaf(p, f, 6.9314718056e-1f);
    p = fmaf(p, f, 1.0f);
    int ni = __float_as_int(r) - 0x4B400000;
    return __int_as_float(__float_as_int(p) + (ni << 23));
}

#define MMA16(c, a, b)                                                          \
    asm volatile("mma.sync.aligned.m16n8k16.row.col.f32.f16.f16.f32 "          \
                 "{%0,%1,%2,%3}, {%4,%5,%6,%7}, {%8,%9}, {%0,%1,%2,%3};"       \
                 : "+f"((c)[0]), "+f"((c)[1]), "+f"((c)[2]), "+f"((c)[3])      \
                 : "r"((a)[0]), "r"((a)[1]), "r"((a)[2]), "r"((a)[3]),         \
                   "r"((b)[0]), "r"((b)[1]))

__device__ __forceinline__ void cp16(uint32_t dst, const void* src) {
    asm volatile("cp.async.cg.shared.global [%0], [%1], 16;" :: "r"(dst), "l"(src));
}
#define CP_COMMIT() asm volatile("cp.async.commit_group;")
#define CP_WAIT1()  asm volatile("cp.async.wait_group 1;")
#define CP_WAIT3()  asm volatile("cp.async.wait_group 3;")

__device__ __forceinline__ void ldsm4(uint32_t* r, uint32_t addr) {
    asm volatile("ldmatrix.sync.aligned.m8n8.x4.shared.b16 {%0,%1,%2,%3}, [%4];"
                 : "=r"(r[0]), "=r"(r[1]), "=r"(r[2]), "=r"(r[3]) : "r"(addr));
}
__device__ __forceinline__ void ldsm4t(uint32_t* r, uint32_t addr) {
    asm volatile("ldmatrix.sync.aligned.m8n8.x4.trans.shared.b16 {%0,%1,%2,%3}, [%4];"
                 : "=r"(r[0]), "=r"(r[1]), "=r"(r[2]), "=r"(r[3]) : "r"(addr));
}
__device__ __forceinline__ uint32_t scvta(const void* p) {
    return (uint32_t)__cvta_generic_to_shared(p);
}

// ---------------------------------------------------------------------------
// fp16 GEMM: C[M,Nall] = A[M,K] @ Bt[Nall,K]^T, fp32 accum.
// BM=128, BN=128, BK=32. 256 thr = 8 warps (2m x 4n), warp tile 64x32.
// 5-stage cp.async pipeline (sound tail via empty commits), ldmatrix frags.
// ---------------------------------------------------------------------------
#define NSTG 5
#define STG_BYTES 10240                 // 128*40 halves * 2B per matrix stage
#define GEMM_SMEM (2 * NSTG * STG_BYTES)   // 102400 B

template<bool OUTH, bool HB, bool RELU, bool RESID>
__global__ void __launch_bounds__(256, 2) gemm_h(const __half* __restrict__ A,
                                                 const __half* __restrict__ Bt,
                                                 const float* __restrict__ bias,
                                                 const float* __restrict__ resid,
                                                 void* __restrict__ Cout,
                                                 int K, int Nall)
{
    extern __shared__ __half sh[];
    __half* As = sh;                     // [NSTG][128*40]
    __half* Bs = sh + NSTG * 5120;       // [NSTG][128*40]
    uint32_t aBase = scvta(As), bBase = scvta(Bs);

    int tid = threadIdx.x, lane = tid & 31, warp = tid >> 5;
    int wm = warp >> 2, wn = warp & 3;
    size_t m0 = (size_t)blockIdx.y * 128;
    int n0 = blockIdx.x * 128;
    const int NT = K >> 5;

    float acc[4][4][4] = {};

    int lrow = tid >> 2, lkc = tid & 3;
    const __half* Ag = A + (m0 + lrow) * (size_t)K + lkc * 8;
    const __half* Bg = Bt + (size_t)(n0 + lrow) * K + lkc * 8;
    uint32_t sOff = (uint32_t)(lrow * 40 + lkc * 8) * 2;

    auto issue = [&](int kt, int st) {
        int k0 = kt * 32;
        uint32_t d = aBase + st * STG_BYTES + sOff;
        cp16(d, Ag + k0);
        cp16(d + 64 * 80, Ag + (size_t)64 * K + k0);
        d = bBase + st * STG_BYTES + sOff;
        cp16(d, Bg + k0);
        cp16(d + 64 * 80, Bg + (size_t)64 * K + k0);
        CP_COMMIT();
    };

    uint32_t aFrag = aBase + (uint32_t)(((wm * 64 + (lane & 15)) * 40 + (lane >> 4) * 8) * 2);
    uint32_t bFrag = bBase + (uint32_t)(((wn * 32 + ((lane >> 4) & 1) * 8 + (lane & 7)) * 40
                                         + ((lane >> 3) & 1) * 8) * 2);

    auto compute = [&](int st) {
        uint32_t so = (uint32_t)(st * STG_BYTES);
#pragma unroll
        for (int ks = 0; ks < 2; ks++) {
            uint32_t ko = so + ks * 32;
            uint32_t a[4][4], bfr[2][4];
#pragma unroll
            for (int mi = 0; mi < 4; mi++) ldsm4(a[mi], aFrag + ko + mi * 1280);
#pragma unroll
            for (int nh = 0; nh < 2; nh++) ldsm4(bfr[nh], bFrag + ko + nh * 1280);
#pragma unroll
            for (int mi = 0; mi < 4; mi++)
#pragma unroll
                for (int ni = 0; ni < 4; ni++)
                    MMA16(acc[mi][ni], a[mi], &bfr[ni >> 1][(ni & 1) * 2]);
        }
    };

    issue(0, 0);
    issue(1, 1);
    issue(2, 2);
    issue(3, 3);
    int stc = 0, sti = 4;
    for (int kt = 0; kt < NT; kt++) {
        CP_WAIT3();            // commits so far = kt+4 -> chunks 0..kt complete
        __syncthreads();       // all warps done with the stage being refilled
        if (kt + 4 < NT) issue(kt + 4, sti);
        else CP_COMMIT();      // keep group-count invariant through the tail
        compute(stc);
        stc = (stc == NSTG - 1) ? 0 : stc + 1;
        sti = (sti == NSTG - 1) ? 0 : sti + 1;
    }

    // ---- epilogue ----
#pragma unroll
    for (int mi = 0; mi < 4; mi++)
#pragma unroll
        for (int ni = 0; ni < 4; ni++) {
            int col = n0 + wn * 32 + ni * 8 + 2 * (lane & 3);
            float bx = 0.f, by = 0.f;
            if (HB) { bx = bias[col]; by = bias[col + 1]; }
#pragma unroll
            for (int rh = 0; rh < 2; rh++) {
                size_t row = m0 + wm * 64 + mi * 16 + (lane >> 2) + rh * 8;
                float v0 = acc[mi][ni][rh * 2 + 0] + bx;
                float v1 = acc[mi][ni][rh * 2 + 1] + by;
                if (RELU) { v0 = fmaxf(v0, 0.f); v1 = fmaxf(v1, 0.f); }
                if (RESID) {
                    const float2 rv = *(const float2*)(resid + row * (size_t)Nall + col);
                    v0 += rv.x; v1 += rv.y;
                }
                if (OUTH) {
                    *(__half2*)((__half*)Cout + row * (size_t)Nall + col) =
                        __floats2half2_rn(v0, v1);
                } else {
                    *(float2*)((float*)Cout + row * (size_t)Nall + col) = make_float2(v0, v1);
                }
            }
        }
}

// ---------------------------------------------------------------------------
// merged weight prep: pack QKV + transpose Wp/W1/W2 to half [n][k]
// ---------------------------------------------------------------------------
#define PK_QKV   442368
#define PK_WP    147456
#define PK_W1    589824
#define PK_TOT   (PK_QKV + PK_WP + PK_W1 + PK_W1)

__global__ void prep_w(const float* __restrict__ Wq, const float* __restrict__ Wk,
                       const float* __restrict__ Wv, const float* __restrict__ Wp,
                       const float* __restrict__ W1, const float* __restrict__ W2,
                       __half* __restrict__ owqkv, __half* __restrict__ owp,
                       __half* __restrict__ ow1, __half* __restrict__ ow2)
{
    int idx = blockIdx.x * 256 + threadIdx.x;
    if (idx < PK_QKV) {
        int mat = idx / 147456;
        int r = idx - mat * 147456;
        int h = r / 24576;
        int r2 = r - h * 24576;
        int c = r2 >> 6;
        int d = r2 & 63;
        const float* W = (mat == 0) ? Wq : (mat == 1) ? Wk : Wv;
        owqkv[(size_t)(mat * CDIM + h * HDIM + d) * CDIM + c] = __float2half(W[r]);
        return;
    }
    idx -= PK_QKV;
    if (idx < PK_WP) {
        int k = idx / CDIM, n = idx - k * CDIM;
        owp[(size_t)n * CDIM + k] = __float2half(Wp[idx]);
        return;
    }
    idx -= PK_WP;
    if (idx < PK_W1) {
        int k = idx / FDIM, n = idx - k * FDIM;
        ow1[(size_t)n * CDIM + k] = __float2half(W1[idx]);
        return;
    }
    idx -= PK_W1;
    {
        int k = idx / CDIM, n = idx - k * CDIM;
        ow2[(size_t)n * FDIM + k] = __float2half(W2[idx]);
    }
}

// ---------------------------------------------------------------------------
// LayerNorm: one warp per token, shfl-only reductions, no barriers.
// ---------------------------------------------------------------------------
__global__ void __launch_bounds__(256) ln_kernel(const float* __restrict__ x,
                                                 const float* __restrict__ g,
                                                 const float* __restrict__ be,
                                                 __half* __restrict__ out)
{
    int lane = threadIdx.x & 31;
    size_t token = (size_t)blockIdx.x * 8 + (threadIdx.x >> 5);
    const float* xr = x + token * CDIM;

    float4 v[3];
#pragma unroll
    for (int p = 0; p < 3; p++) v[p] = *(const float4*)(xr + lane * 4 + p * 128);

    float s = 0.f;
#pragma unroll
    for (int p = 0; p < 3; p++) s += (v[p].x + v[p].y) + (v[p].z + v[p].w);
#pragma unroll
    for (int o = 16; o; o >>= 1) s += __shfl_xor_sync(0xFFFFFFFFu, s, o);
    float mu = s * (1.0f / 384.0f);

    float ss = 0.f;
#pragma unroll
    for (int p = 0; p < 3; p++) {
        float a0 = v[p].x - mu, a1 = v[p].y - mu, a2 = v[p].z - mu, a3 = v[p].w - mu;
        ss += (a0 * a0 + a1 * a1) + (a2 * a2 + a3 * a3);
    }
#pragma unroll
    for (int o = 16; o; o >>= 1) ss += __shfl_xor_sync(0xFFFFFFFFu, ss, o);
    float rstd = rsqrtf(ss * (1.0f / 384.0f) + 1e-5f);

    __half* orow = out + token * CDIM;
#pragma unroll
    for (int p = 0; p < 3; p++) {
        int c = lane * 4 + p * 128;
        float4 gv = *(const float4*)(g + c);
        float4 bv = *(const float4*)(be + c);
        __half2 h0 = __floats2half2_rn((v[p].x - mu) * rstd * gv.x + bv.x,
                                       (v[p].y - mu) * rstd * gv.y + bv.y);
        __half2 h1 = __floats2half2_rn((v[p].z - mu) * rstd * gv.z + bv.z,
                                       (v[p].w - mu) * rstd * gv.w + bv.w);
        uint2 pk = make_uint2(*(uint32_t*)&h0, *(uint32_t*)&h1);
        *(uint2*)(orow + c) = pk;
    }
}

// ---------------------------------------------------------------------------
// Flash attention, fp16 mma + ldmatrix, cp.async double-buffered K/V.
// Grid (2, 1536), 256 thr = 8 warps (4m x 2n). P via smem.
// ---------------------------------------------------------------------------
#define ATT_SMEM 74752

__global__ void __launch_bounds__(256) attn_mma(const __half* __restrict__ qkv,
                                                __half* __restrict__ Og)
{
    extern __shared__ __half sma[];
    __half* Qs = sma;                    // 9216
    __half* Ks = Qs + 9216;              // 2 * 4608
    __half* Vs = Ks + 9216;              // 2 * 4608
    __half* Ps = Vs + 9216;              // 9216
    float* lsum = (float*)(Ps + 9216);   // 256 floats

    uint32_t qB = scvta(Qs), kB = scvta(Ks), vB = scvta(Vs), pB = scvta(Ps);

    int qt = blockIdx.x;
    int bh = blockIdx.y;
    int b = bh / NHEAD, h = bh % NHEAD;
    int tid = threadIdx.x, lane = tid & 31, warp = tid >> 5;
    int wm = warp >> 1, wn = warp & 1;
    int lr = lane >> 2;

    size_t tokbase = (size_t)b * TLEN;
    const __half* Kg = qkv + tokbase * QKVC + CDIM + h * HDIM;
    const __half* Vg = qkv + tokbase * QKVC + 2 * CDIM + h * HDIM;

    int qrow[4], qc8[4];
#pragma unroll
    for (int i = 0; i < 4; i++) { int f = tid + i * 256; qrow[i] = f >> 3; qc8[i] = f & 7; }
    int krow0 = tid >> 3, kc8 = tid & 7;

    auto prefetch_kv = [&](int ci) {
        uint32_t buf = (uint32_t)((ci & 1) * 4608 * 2);
        int srow0 = ci * 64;
#pragma unroll
        for (int i = 0; i < 2; i++) {
            int srow = krow0 + i * 32;
            uint32_t off = (uint32_t)((srow * 72 + kc8 * 8) * 2);
            cp16(kB + buf + off, Kg + (size_t)(srow0 + srow) * QKVC + kc8 * 8);
            cp16(vB + buf + off, Vg + (size_t)(srow0 + srow) * QKVC + kc8 * 8);
        }
    };

#pragma unroll
    for (int i = 0; i < 4; i++) {
        cp16(qB + (uint32_t)((qrow[i] * 72 + qc8[i] * 8) * 2),
             qkv + (tokbase + qt * 128 + qrow[i]) * QKVC + h * HDIM + qc8[i] * 8);
    }
    prefetch_kv(0);
    CP_COMMIT();

    float o[2][4][4] = {};
    float lacc[2][2] = {};

    uint32_t aOff = (uint32_t)(((wm * 32 + (lane & 15)) * 72 + (lane >> 4) * 8) * 2);
    uint32_t bOffK = (uint32_t)(((wn * 32 + ((lane >> 4) & 1) * 8 + (lane & 7)) * 72
                                 + ((lane >> 3) & 1) * 8) * 2);
    uint32_t bOffV = (uint32_t)(((((lane >> 3) & 1) * 8 + (lane & 7)) * 72
                                 + wn * 32 + ((lane >> 4) & 1) * 8) * 2);

    int nchunk = 2 * (qt + 1);
    for (int ci = 0; ci < nchunk; ci++) {
        int s0 = ci * 64;
        uint32_t kbuf = kB + (uint32_t)((ci & 1) * 9216);
        uint32_t vbuf = vB + (uint32_t)((ci & 1) * 9216);

        __syncthreads();
        if (ci + 1 < nchunk) { prefetch_kv(ci + 1); CP_COMMIT(); }
        else CP_COMMIT();
        CP_WAIT1();
        __syncthreads();

        // S = Q @ K^T
        float s[2][4][4] = {};
#pragma unroll
        for (int ks = 0; ks < 4; ks++) {
            uint32_t ko = ks * 32;
            uint32_t a[2][4], bfr[2][4];
#pragma unroll
            for (int mi = 0; mi < 2; mi++) ldsm4(a[mi], qB + aOff + ko + mi * 2304);
#pragma unroll
            for (int nh = 0; nh < 2; nh++) ldsm4(bfr[nh], kbuf + bOffK + ko + nh * 2304);
#pragma unroll
            for (int mi = 0; mi < 2; mi++)
#pragma unroll
                for (int ni = 0; ni < 4; ni++)
                    MMA16(s[mi][ni], a[mi], &bfr[ni >> 1][(ni & 1) * 2]);
        }

        // mask + exp + row sums + store P
        bool domask = (s0 + 63 > qt * 128);
#pragma unroll
        for (int mi = 0; mi < 2; mi++) {
            int row0 = qt * 128 + wm * 32 + mi * 16 + lr;
            int prow = wm * 32 + mi * 16 + lr;
#pragma unroll
            for (int ni = 0; ni < 4; ni++) {
                int col0 = s0 + wn * 32 + ni * 8 + 2 * (lane & 3);
#pragma unroll
                for (int e = 0; e < 4; e++) {
                    int rr = row0 + (e >> 1) * 8;
                    int cc = col0 + (e & 1);
                    float p = (domask && cc > rr) ? 0.f : fast_exp_scaled(s[mi][ni][e]);
                    s[mi][ni][e] = p;
                    lacc[mi][e >> 1] += p;
                }
                int pcol = wn * 32 + ni * 8 + 2 * (lane & 3);
                *(__half2*)(Ps + prow * 72 + pcol) =
                    __floats2half2_rn(s[mi][ni][0], s[mi][ni][1]);
                *(__half2*)(Ps + (prow + 8) * 72 + pcol) =
                    __floats2half2_rn(s[mi][ni][2], s[mi][ni][3]);
            }
        }
        __syncthreads();

        // O += P @ V
#pragma unroll
        for (int ks = 0; ks < 4; ks++) {
            uint32_t a[2][4], bfr[2][4];
#pragma unroll
            for (int mi = 0; mi < 2; mi++) ldsm4(a[mi], pB + aOff + ks * 32 + mi * 2304);
#pragma unroll
            for (int nh = 0; nh < 2; nh++)
                ldsm4t(bfr[nh], vbuf + bOffV + ks * 2304 + nh * 32);
#pragma unroll
            for (int mi = 0; mi < 2; mi++)
#pragma unroll
                for (int ni = 0; ni < 4; ni++)
                    MMA16(o[mi][ni], a[mi], &bfr[ni >> 1][(ni & 1) * 2]);
        }
    }

    // reduce row sums, publish, combine
#pragma unroll
    for (int mi = 0; mi < 2; mi++)
#pragma unroll
        for (int e = 0; e < 2; e++) {
            lacc[mi][e] += __shfl_xor_sync(0xFFFFFFFFu, lacc[mi][e], 1);
            lacc[mi][e] += __shfl_xor_sync(0xFFFFFFFFu, lacc[mi][e], 2);
        }
    if ((lane & 3) == 0) {
#pragma unroll
        for (int mi = 0; mi < 2; mi++) {
            lsum[wn * 128 + wm * 32 + mi * 16 + lr] = lacc[mi][0];
            lsum[wn * 128 + wm * 32 + mi * 16 + lr + 8] = lacc[mi][1];
        }
    }
    __syncthreads();

    // normalize + store (half)
#pragma unroll
    for (int mi = 0; mi < 2; mi++) {
        int prow = wm * 32 + mi * 16 + lr;
        float inv0 = 1.f / (lsum[prow] + lsum[128 + prow]);
        float inv1 = 1.f / (lsum[prow + 8] + lsum[128 + prow + 8]);
        size_t grow = tokbase + qt * 128 + prow;
#pragma unroll
        for (int ni = 0; ni < 4; ni++) {
            int col = h * HDIM + wn * 32 + ni * 8 + 2 * (lane & 3);
            *(__half2*)(Og + grow * CDIM + col) =
                __floats2half2_rn(o[mi][ni][0] * inv0, o[mi][ni][1] * inv0);
            *(__half2*)(Og + (grow + 8) * CDIM + col) =
                __floats2half2_rn(o[mi][ni][2] * inv1, o[mi][ni][3] * inv1);
        }
    }
}

// ---------------------------------------------------------------------------
// Host launch
// ---------------------------------------------------------------------------
extern "C" void kernel_launch(void* const* d_in, const int* in_sizes, int n_in,
                              void* d_out, int out_size)
{
    const float* x   = (const float*)d_in[0];
    const float* Wq  = (const float*)d_in[1];
    const float* Wk  = (const float*)d_in[2];
    const float* Wv  = (const float*)d_in[3];
    const float* Wp  = (const float*)d_in[4];
    const float* bp  = (const float*)d_in[5];
    const float* W1  = (const float*)d_in[6];
    const float* b1  = (const float*)d_in[7];
    const float* W2  = (const float*)d_in[8];
    const float* b2  = (const float*)d_in[9];
    const float* g1  = (const float*)d_in[10];
    const float* be1 = (const float*)d_in[11];
    const float* g2  = (const float*)d_in[12];
    const float* be2 = (const float*)d_in[13];
    float* out = (float*)d_out;

    __half *h, *qkv, *attn, *ff, *wqkv, *wp, *w1, *w2;
    float *xmid;
    cudaGetSymbolAddress((void**)&h,    g_h);
    cudaGetSymbolAddress((void**)&qkv,  g_qkv);
    cudaGetSymbolAddress((void**)&attn, g_attn);
    cudaGetSymbolAddress((void**)&xmid, g_xmid);
    cudaGetSymbolAddress((void**)&ff,   g_ff);
    cudaGetSymbolAddress((void**)&wqkv, g_wqkv);
    cudaGetSymbolAddress((void**)&wp,   g_wp);
    cudaGetSymbolAddress((void**)&w1,   g_w1);
    cudaGetSymbolAddress((void**)&w2,   g_w2);

    cudaFuncSetAttribute(gemm_h<true, false, false, false>,
                         cudaFuncAttributeMaxDynamicSharedMemorySize, GEMM_SMEM);
    cudaFuncSetAttribute(gemm_h<false, true, false, true>,
                         cudaFuncAttributeMaxDynamicSharedMemorySize, GEMM_SMEM);
    cudaFuncSetAttribute(gemm_h<true, true, true, false>,
                         cudaFuncAttributeMaxDynamicSharedMemorySize, GEMM_SMEM);
    cudaFuncSetAttribute(attn_mma, cudaFuncAttributeMaxDynamicSharedMemorySize, ATT_SMEM);

    // 0. merged weight prep
    prep_w<<<(PK_TOT + 255) / 256, 256>>>(Wq, Wk, Wv, Wp, W1, W2, wqkv, wp, w1, w2);
    // 1. LN1 -> h (half)
    ln_kernel<<<NTOK / 8, 256>>>(x, g1, be1, h);
    // 2. QKV GEMM -> qkv (half)
    gemm_h<true, false, false, false><<<dim3(QKVC / 128, NTOK / 128), 256, GEMM_SMEM>>>(
        h, wqkv, nullptr, nullptr, qkv, CDIM, QKVC);
    // 3. flash attention -> attn (half)
    attn_mma<<<dim3(2, TLEN * NHEAD), 256, ATT_SMEM>>>(qkv, attn);
    // 4. proj + bias + residual(x) -> xmid (fp32)
    gemm_h<false, true, false, true><<<dim3(CDIM / 128, NTOK / 128), 256, GEMM_SMEM>>>(
        attn, wp, bp, x, xmid, CDIM, CDIM);
    // 5. LN2 -> h (half)
    ln_kernel<<<NTOK / 8, 256>>>(xmid, g2, be2, h);
    // 6. FF1 + bias + relu -> ff (half)
    gemm_h<true, true, true, false><<<dim3(FDIM / 128, NTOK / 128), 256, GEMM_SMEM>>>(
        h, w1, b1, nullptr, ff, CDIM, FDIM);
    // 7. FF2 + bias + residual(xmid) -> out (fp32)
    gemm_h<false, true, false, true><<<dim3(CDIM / 128, NTOK / 128), 256, GEMM_SMEM>>>(
        ff, w2, b2, xmid, out, FDIM, CDIM);
}

// round 17
// speedup vs baseline: 1.1412x; 1.0399x over previous
#include <cuda_runtime.h>
#include <cuda_fp16.h>
#include <cstdint>

// ---------------------------------------------------------------------------
// TransformerBlock: B=256, T=256, C=384, H=6, D=64, F=1536, N=B*T=65536
// fp16 mma.sync (fp32 accum), cp.async pipelines, ldmatrix frags.
// GEMM: R11 config (BM=128 BN=128, 4-stage). Attn: triple-buffered K/V.
// ---------------------------------------------------------------------------

#define NTOK  65536
#define CDIM  384
#define NHEAD 6
#define HDIM  64
#define FDIM  1536
#define TLEN  256
#define QKVC  1152

__device__ __half g_h   [(size_t)NTOK * CDIM];
__device__ __half g_qkv [(size_t)NTOK * QKVC];
__device__ __half g_attn[(size_t)NTOK * CDIM];
__device__ float  g_xmid[(size_t)NTOK * CDIM];
__device__ __half g_ff  [(size_t)NTOK * FDIM];
__device__ __half g_wqkv[(size_t)QKVC * CDIM];
__device__ __half g_wp  [(size_t)CDIM * CDIM];
__device__ __half g_w1  [(size_t)FDIM * CDIM];
__device__ __half g_w2  [(size_t)CDIM * FDIM];

// ---------------------------------------------------------------------------
// helpers
// ---------------------------------------------------------------------------
__device__ __forceinline__ float fast_exp_scaled(float dot) {
    float y = dot * 0.1803368801111244f;           // 0.125 * log2(e)
    float r = y + 12582912.0f;
    float nf = r - 12582912.0f;
    float f = y - nf;
    float p = 1.3333558146e-3f;
    p = fmaf(p, f, 9.6181291076e-3f);
    p = fmaf(p, f, 5.5504108664e-2f);
    p = fmaf(p, f, 2.4022650696e-1f);
    p = fmaf(p, f, 6.9314718056e-1f);
    p = fmaf(p, f, 1.0f);
    int ni = __float_as_int(r) - 0x4B400000;
    return __int_as_float(__float_as_int(p) + (ni << 23));
}

#define MMA16(c, a, b)                                                          \
    asm volatile("mma.sync.aligned.m16n8k16.row.col.f32.f16.f16.f32 "          \
                 "{%0,%1,%2,%3}, {%4,%5,%6,%7}, {%8,%9}, {%0,%1,%2,%3};"       \
                 : "+f"((c)[0]), "+f"((c)[1]), "+f"((c)[2]), "+f"((c)[3])      \
                 : "r"((a)[0]), "r"((a)[1]), "r"((a)[2]), "r"((a)[3]),         \
                   "r"((b)[0]), "r"((b)[1]))

__device__ __forceinline__ void cp16(uint32_t dst, const void* src) {
    asm volatile("cp.async.cg.shared.global [%0], [%1], 16;" :: "r"(dst), "l"(src));
}
#define CP_COMMIT() asm volatile("cp.async.commit_group;")
#define CP_WAIT2()  asm volatile("cp.async.wait_group 2;")

__device__ __forceinline__ void ldsm4(uint32_t* r, uint32_t addr) {
    asm volatile("ldmatrix.sync.aligned.m8n8.x4.shared.b16 {%0,%1,%2,%3}, [%4];"
                 : "=r"(r[0]), "=r"(r[1]), "=r"(r[2]), "=r"(r[3]) : "r"(addr));
}
__device__ __forceinline__ void ldsm4t(uint32_t* r, uint32_t addr) {
    asm volatile("ldmatrix.sync.aligned.m8n8.x4.trans.shared.b16 {%0,%1,%2,%3}, [%4];"
                 : "=r"(r[0]), "=r"(r[1]), "=r"(r[2]), "=r"(r[3]) : "r"(addr));
}
__device__ __forceinline__ uint32_t scvta(const void* p) {
    return (uint32_t)__cvta_generic_to_shared(p);
}

// ---------------------------------------------------------------------------
// fp16 GEMM: C[M,Nall] = A[M,K] @ Bt[Nall,K]^T, fp32 accum.
// BM=128, BN=128, BK=32. 256 thr = 8 warps (2m x 4n), warp tile 64x32.
// 4-stage cp.async pipeline (sound tail via empty commits), ldmatrix frags.
// (Exact R11 config — fastest measured.)
// ---------------------------------------------------------------------------
#define GEMM_SMEM 81920   // 2 matrices * 4 stages * 128*40 halves * 2B

template<bool OUTH, bool HB, bool RELU, bool RESID>
__global__ void __launch_bounds__(256, 2) gemm_h(const __half* __restrict__ A,
                                                 const __half* __restrict__ Bt,
                                                 const float* __restrict__ bias,
                                                 const float* __restrict__ resid,
                                                 void* __restrict__ Cout,
                                                 int K, int Nall)
{
    extern __shared__ __half sh[];
    __half* As = sh;                 // [4][128*40]
    __half* Bs = sh + 4 * 5120;      // [4][128*40]
    uint32_t aBase = scvta(As), bBase = scvta(Bs);

    int tid = threadIdx.x, lane = tid & 31, warp = tid >> 5;
    int wm = warp >> 2, wn = warp & 3;
    size_t m0 = (size_t)blockIdx.y * 128;
    int n0 = blockIdx.x * 128;
    const int NT = K >> 5;

    float acc[4][4][4] = {};

    int lrow = tid >> 2, lkc = tid & 3;
    const __half* Ag = A + (m0 + lrow) * (size_t)K + lkc * 8;
    const __half* Bg = Bt + (size_t)(n0 + lrow) * K + lkc * 8;
    uint32_t sOff = (uint32_t)(lrow * 40 + lkc * 8) * 2;

    auto issue = [&](int kt) {
        int st = kt & 3;
        int k0 = kt * 32;
        uint32_t d = aBase + st * 10240 + sOff;
        cp16(d, Ag + k0);
        cp16(d + 64 * 80, Ag + (size_t)64 * K + k0);
        d = bBase + st * 10240 + sOff;
        cp16(d, Bg + k0);
        cp16(d + 64 * 80, Bg + (size_t)64 * K + k0);
        CP_COMMIT();
    };

    uint32_t aFrag = aBase + (uint32_t)(((wm * 64 + (lane & 15)) * 40 + (lane >> 4) * 8) * 2);
    uint32_t bFrag = bBase + (uint32_t)(((wn * 32 + ((lane >> 4) & 1) * 8 + (lane & 7)) * 40
                                         + ((lane >> 3) & 1) * 8) * 2);

    auto compute = [&](int st) {
        uint32_t so = (uint32_t)(st * 10240);
#pragma unroll
        for (int ks = 0; ks < 2; ks++) {
            uint32_t ko = so + ks * 32;
            uint32_t a[4][4], bfr[2][4];
#pragma unroll
            for (int mi = 0; mi < 4; mi++) ldsm4(a[mi], aFrag + ko + mi * 1280);
#pragma unroll
            for (int nh = 0; nh < 2; nh++) ldsm4(bfr[nh], bFrag + ko + nh * 1280);
#pragma unroll
            for (int mi = 0; mi < 4; mi++)
#pragma unroll
                for (int ni = 0; ni < 4; ni++)
                    MMA16(acc[mi][ni], a[mi], &bfr[ni >> 1][(ni & 1) * 2]);
        }
    };

    issue(0);
    issue(1);
    issue(2);
    for (int kt = 0; kt < NT; kt++) {
        CP_WAIT2();            // commits so far = kt+3 -> chunks 0..kt complete
        __syncthreads();       // all warps done with stage (kt-1)&3
        if (kt + 3 < NT) issue(kt + 3);
        else CP_COMMIT();      // keep group-count invariant through the tail
        compute(kt & 3);
    }

    // ---- epilogue ----
#pragma unroll
    for (int mi = 0; mi < 4; mi++)
#pragma unroll
        for (int ni = 0; ni < 4; ni++) {
            int col = n0 + wn * 32 + ni * 8 + 2 * (lane & 3);
            float bx = 0.f, by = 0.f;
            if (HB) { bx = bias[col]; by = bias[col + 1]; }
#pragma unroll
            for (int rh = 0; rh < 2; rh++) {
                size_t row = m0 + wm * 64 + mi * 16 + (lane >> 2) + rh * 8;
                float v0 = acc[mi][ni][rh * 2 + 0] + bx;
                float v1 = acc[mi][ni][rh * 2 + 1] + by;
                if (RELU) { v0 = fmaxf(v0, 0.f); v1 = fmaxf(v1, 0.f); }
                if (RESID) {
                    const float2 rv = *(const float2*)(resid + row * (size_t)Nall + col);
                    v0 += rv.x; v1 += rv.y;
                }
                if (OUTH) {
                    *(__half2*)((__half*)Cout + row * (size_t)Nall + col) =
                        __floats2half2_rn(v0, v1);
                } else {
                    *(float2*)((float*)Cout + row * (size_t)Nall + col) = make_float2(v0, v1);
                }
            }
        }
}

// ---------------------------------------------------------------------------
// merged weight prep: pack QKV + transpose Wp/W1/W2 to half [n][k]
// ---------------------------------------------------------------------------
#define PK_QKV   442368
#define PK_WP    147456
#define PK_W1    589824
#define PK_TOT   (PK_QKV + PK_WP + PK_W1 + PK_W1)

__global__ void prep_w(const float* __restrict__ Wq, const float* __restrict__ Wk,
                       const float* __restrict__ Wv, const float* __restrict__ Wp,
                       const float* __restrict__ W1, const float* __restrict__ W2,
                       __half* __restrict__ owqkv, __half* __restrict__ owp,
                       __half* __restrict__ ow1, __half* __restrict__ ow2)
{
    int idx = blockIdx.x * 256 + threadIdx.x;
    if (idx < PK_QKV) {
        int mat = idx / 147456;
        int r = idx - mat * 147456;
        int h = r / 24576;
        int r2 = r - h * 24576;
        int c = r2 >> 6;
        int d = r2 & 63;
        const float* W = (mat == 0) ? Wq : (mat == 1) ? Wk : Wv;
        owqkv[(size_t)(mat * CDIM + h * HDIM + d) * CDIM + c] = __float2half(W[r]);
        return;
    }
    idx -= PK_QKV;
    if (idx < PK_WP) {
        int k = idx / CDIM, n = idx - k * CDIM;
        owp[(size_t)n * CDIM + k] = __float2half(Wp[idx]);
        return;
    }
    idx -= PK_WP;
    if (idx < PK_W1) {
        int k = idx / FDIM, n = idx - k * FDIM;
        ow1[(size_t)n * CDIM + k] = __float2half(W1[idx]);
        return;
    }
    idx -= PK_W1;
    {
        int k = idx / CDIM, n = idx - k * CDIM;
        ow2[(size_t)n * FDIM + k] = __float2half(W2[idx]);
    }
}

// ---------------------------------------------------------------------------
// LayerNorm: one warp per token, shfl-only reductions, no barriers.
// ---------------------------------------------------------------------------
__global__ void __launch_bounds__(256) ln_kernel(const float* __restrict__ x,
                                                 const float* __restrict__ g,
                                                 const float* __restrict__ be,
                                                 __half* __restrict__ out)
{
    int lane = threadIdx.x & 31;
    size_t token = (size_t)blockIdx.x * 8 + (threadIdx.x >> 5);
    const float* xr = x + token * CDIM;

    float4 v[3];
#pragma unroll
    for (int p = 0; p < 3; p++) v[p] = *(const float4*)(xr + lane * 4 + p * 128);

    float s = 0.f;
#pragma unroll
    for (int p = 0; p < 3; p++) s += (v[p].x + v[p].y) + (v[p].z + v[p].w);
#pragma unroll
    for (int o = 16; o; o >>= 1) s += __shfl_xor_sync(0xFFFFFFFFu, s, o);
    float mu = s * (1.0f / 384.0f);

    float ss = 0.f;
#pragma unroll
    for (int p = 0; p < 3; p++) {
        float a0 = v[p].x - mu, a1 = v[p].y - mu, a2 = v[p].z - mu, a3 = v[p].w - mu;
        ss += (a0 * a0 + a1 * a1) + (a2 * a2 + a3 * a3);
    }
#pragma unroll
    for (int o = 16; o; o >>= 1) ss += __shfl_xor_sync(0xFFFFFFFFu, ss, o);
    float rstd = rsqrtf(ss * (1.0f / 384.0f) + 1e-5f);

    __half* orow = out + token * CDIM;
#pragma unroll
    for (int p = 0; p < 3; p++) {
        int c = lane * 4 + p * 128;
        float4 gv = *(const float4*)(g + c);
        float4 bv = *(const float4*)(be + c);
        __half2 h0 = __floats2half2_rn((v[p].x - mu) * rstd * gv.x + bv.x,
                                       (v[p].y - mu) * rstd * gv.y + bv.y);
        __half2 h1 = __floats2half2_rn((v[p].z - mu) * rstd * gv.z + bv.z,
                                       (v[p].w - mu) * rstd * gv.w + bv.w);
        uint2 pk = make_uint2(*(uint32_t*)&h0, *(uint32_t*)&h1);
        *(uint2*)(orow + c) = pk;
    }
}

// ---------------------------------------------------------------------------
// Flash attention, fp16 mma + ldmatrix, cp.async TRIPLE-buffered K/V
// (2 chunks in flight). Grid (2, 1536), 256 thr = 8 warps (4m x 2n).
// smem: Qs 128x72 | Ks[3] 64x72 | Vs[3] 64x72 | Ps 128x72 | lsum 2x128 f32
// ---------------------------------------------------------------------------
#define ATT_SMEM 93184

__global__ void __launch_bounds__(256) attn_mma(const __half* __restrict__ qkv,
                                                __half* __restrict__ Og)
{
    extern __shared__ __half sma[];
    __half* Qs = sma;                    // 9216
    __half* Ks = Qs + 9216;              // 3 * 4608
    __half* Vs = Ks + 13824;             // 3 * 4608
    __half* Ps = Vs + 13824;             // 9216
    float* lsum = (float*)(Ps + 9216);   // 256 floats

    uint32_t qB = scvta(Qs), kB = scvta(Ks), vB = scvta(Vs), pB = scvta(Ps);

    int qt = blockIdx.x;
    int bh = blockIdx.y;
    int b = bh / NHEAD, h = bh % NHEAD;
    int tid = threadIdx.x, lane = tid & 31, warp = tid >> 5;
    int wm = warp >> 1, wn = warp & 1;
    int lr = lane >> 2;

    size_t tokbase = (size_t)b * TLEN;
    const __half* Kg = qkv + tokbase * QKVC + CDIM + h * HDIM;
    const __half* Vg = qkv + tokbase * QKVC + 2 * CDIM + h * HDIM;

    int qrow[4], qc8[4];
#pragma unroll
    for (int i = 0; i < 4; i++) { int f = tid + i * 256; qrow[i] = f >> 3; qc8[i] = f & 7; }
    int krow0 = tid >> 3, kc8 = tid & 7;

    auto prefetch_kv = [&](int ci, int buf3) {
        uint32_t buf = (uint32_t)(buf3 * 4608 * 2);
        int srow0 = ci * 64;
#pragma unroll
        for (int i = 0; i < 2; i++) {
            int srow = krow0 + i * 32;
            uint32_t off = (uint32_t)((srow * 72 + kc8 * 8) * 2);
            cp16(kB + buf + off, Kg + (size_t)(srow0 + srow) * QKVC + kc8 * 8);
            cp16(vB + buf + off, Vg + (size_t)(srow0 + srow) * QKVC + kc8 * 8);
        }
    };

    int nchunk = 2 * (qt + 1);

    // group 0: Q tile + chunk 0 K/V
#pragma unroll
    for (int i = 0; i < 4; i++) {
        cp16(qB + (uint32_t)((qrow[i] * 72 + qc8[i] * 8) * 2),
             qkv + (tokbase + qt * 128 + qrow[i]) * QKVC + h * HDIM + qc8[i] * 8);
    }
    prefetch_kv(0, 0);
    CP_COMMIT();
    // group 1: chunk 1 (or empty)
    if (1 < nchunk) prefetch_kv(1, 1);
    CP_COMMIT();

    float o[2][4][4] = {};
    float lacc[2][2] = {};

    uint32_t aOff = (uint32_t)(((wm * 32 + (lane & 15)) * 72 + (lane >> 4) * 8) * 2);
    uint32_t bOffK = (uint32_t)(((wn * 32 + ((lane >> 4) & 1) * 8 + (lane & 7)) * 72
                                 + ((lane >> 3) & 1) * 8) * 2);
    uint32_t bOffV = (uint32_t)(((((lane >> 3) & 1) * 8 + (lane & 7)) * 72
                                 + wn * 32 + ((lane >> 4) & 1) * 8) * 2);

    int bufc = 0;        // buffer of chunk ci
    int bufi = 2;        // buffer for chunk ci+2
    for (int ci = 0; ci < nchunk; ci++) {
        int s0 = ci * 64;
        uint32_t kbuf = kB + (uint32_t)(bufc * 9216);
        uint32_t vbuf = vB + (uint32_t)(bufc * 9216);

        __syncthreads();                      // iter ci-1 reads of buf bufi done
        if (ci + 2 < nchunk) prefetch_kv(ci + 2, bufi);
        CP_COMMIT();                          // commits = ci+3
        CP_WAIT2();                           // groups 0..ci complete -> chunk ci landed
        __syncthreads();                      // visible to all warps

        // S = Q @ K^T
        float s[2][4][4] = {};
#pragma unroll
        for (int ks = 0; ks < 4; ks++) {
            uint32_t ko = ks * 32;
            uint32_t a[2][4], bfr[2][4];
#pragma unroll
            for (int mi = 0; mi < 2; mi++) ldsm4(a[mi], qB + aOff + ko + mi * 2304);
#pragma unroll
            for (int nh = 0; nh < 2; nh++) ldsm4(bfr[nh], kbuf + bOffK + ko + nh * 2304);
#pragma unroll
            for (int mi = 0; mi < 2; mi++)
#pragma unroll
                for (int ni = 0; ni < 4; ni++)
                    MMA16(s[mi][ni], a[mi], &bfr[ni >> 1][(ni & 1) * 2]);
        }

        // mask + exp + row sums + store P
        bool domask = (s0 + 63 > qt * 128);
#pragma unroll
        for (int mi = 0; mi < 2; mi++) {
            int row0 = qt * 128 + wm * 32 + mi * 16 + lr;
            int prow = wm * 32 + mi * 16 + lr;
#pragma unroll
            for (int ni = 0; ni < 4; ni++) {
                int col0 = s0 + wn * 32 + ni * 8 + 2 * (lane & 3);
#pragma unroll
                for (int e = 0; e < 4; e++) {
                    int rr = row0 + (e >> 1) * 8;
                    int cc = col0 + (e & 1);
                    float p = (domask && cc > rr) ? 0.f : fast_exp_scaled(s[mi][ni][e]);
                    s[mi][ni][e] = p;
                    lacc[mi][e >> 1] += p;
                }
                int pcol = wn * 32 + ni * 8 + 2 * (lane & 3);
                *(__half2*)(Ps + prow * 72 + pcol) =
                    __floats2half2_rn(s[mi][ni][0], s[mi][ni][1]);
                *(__half2*)(Ps + (prow + 8) * 72 + pcol) =
                    __floats2half2_rn(s[mi][ni][2], s[mi][ni][3]);
            }
        }
        __syncthreads();

        // O += P @ V
#pragma unroll
        for (int ks = 0; ks < 4; ks++) {
            uint32_t a[2][4], bfr[2][4];
#pragma unroll
            for (int mi = 0; mi < 2; mi++) ldsm4(a[mi], pB + aOff + ks * 32 + mi * 2304);
#pragma unroll
            for (int nh = 0; nh < 2; nh++)
                ldsm4t(bfr[nh], vbuf + bOffV + ks * 2304 + nh * 32);
#pragma unroll
            for (int mi = 0; mi < 2; mi++)
#pragma unroll
                for (int ni = 0; ni < 4; ni++)
                    MMA16(o[mi][ni], a[mi], &bfr[ni >> 1][(ni & 1) * 2]);
        }

        bufc = (bufc == 2) ? 0 : bufc + 1;
        bufi = (bufi == 2) ? 0 : bufi + 1;
    }

    // reduce row sums, publish, combine
#pragma unroll
    for (int mi = 0; mi < 2; mi++)
#pragma unroll
        for (int e = 0; e < 2; e++) {
            lacc[mi][e] += __shfl_xor_sync(0xFFFFFFFFu, lacc[mi][e], 1);
            lacc[mi][e] += __shfl_xor_sync(0xFFFFFFFFu, lacc[mi][e], 2);
        }
    if ((lane & 3) == 0) {
#pragma unroll
        for (int mi = 0; mi < 2; mi++) {
            lsum[wn * 128 + wm * 32 + mi * 16 + lr] = lacc[mi][0];
            lsum[wn * 128 + wm * 32 + mi * 16 + lr + 8] = lacc[mi][1];
        }
    }
    __syncthreads();

    // normalize + store (half)
#pragma unroll
    for (int mi = 0; mi < 2; mi++) {
        int prow = wm * 32 + mi * 16 + lr;
        float inv0 = 1.f / (lsum[prow] + lsum[128 + prow]);
        float inv1 = 1.f / (lsum[prow + 8] + lsum[128 + prow + 8]);
        size_t grow = tokbase + qt * 128 + prow;
#pragma unroll
        for (int ni = 0; ni < 4; ni++) {
            int col = h * HDIM + wn * 32 + ni * 8 + 2 * (lane & 3);
            *(__half2*)(Og + grow * CDIM + col) =
                __floats2half2_rn(o[mi][ni][0] * inv0, o[mi][ni][1] * inv0);
            *(__half2*)(Og + (grow + 8) * CDIM + col) =
                __floats2half2_rn(o[mi][ni][2] * inv1, o[mi][ni][3] * inv1);
        }
    }
}

// ---------------------------------------------------------------------------
// Host launch
// ---------------------------------------------------------------------------
extern "C" void kernel_launch(void* const* d_in, const int* in_sizes, int n_in,
                              void* d_out, int out_size)
{
    const float* x   = (const float*)d_in[0];
    const float* Wq  = (const float*)d_in[1];
    const float* Wk  = (const float*)d_in[2];
    const float* Wv  = (const float*)d_in[3];
    const float* Wp  = (const float*)d_in[4];
    const float* bp  = (const float*)d_in[5];
    const float* W1  = (const float*)d_in[6];
    const float* b1  = (const float*)d_in[7];
    const float* W2  = (const float*)d_in[8];
    const float* b2  = (const float*)d_in[9];
    const float* g1  = (const float*)d_in[10];
    const float* be1 = (const float*)d_in[11];
    const float* g2  = (const float*)d_in[12];
    const float* be2 = (const float*)d_in[13];
    float* out = (float*)d_out;

    __half *h, *qkv, *attn, *ff, *wqkv, *wp, *w1, *w2;
    float *xmid;
    cudaGetSymbolAddress((void**)&h,    g_h);
    cudaGetSymbolAddress((void**)&qkv,  g_qkv);
    cudaGetSymbolAddress((void**)&attn, g_attn);
    cudaGetSymbolAddress((void**)&xmid, g_xmid);
    cudaGetSymbolAddress((void**)&ff,   g_ff);
    cudaGetSymbolAddress((void**)&wqkv, g_wqkv);
    cudaGetSymbolAddress((void**)&wp,   g_wp);
    cudaGetSymbolAddress((void**)&w1,   g_w1);
    cudaGetSymbolAddress((void**)&w2,   g_w2);

    cudaFuncSetAttribute(gemm_h<true, false, false, false>,
                         cudaFuncAttributeMaxDynamicSharedMemorySize, GEMM_SMEM);
    cudaFuncSetAttribute(gemm_h<false, true, false, true>,
                         cudaFuncAttributeMaxDynamicSharedMemorySize, GEMM_SMEM);
    cudaFuncSetAttribute(gemm_h<true, true, true, false>,
                         cudaFuncAttributeMaxDynamicSharedMemorySize, GEMM_SMEM);
    cudaFuncSetAttribute(attn_mma, cudaFuncAttributeMaxDynamicSharedMemorySize, ATT_SMEM);

    // 0. merged weight prep
    prep_w<<<(PK_TOT + 255) / 256, 256>>>(Wq, Wk, Wv, Wp, W1, W2, wqkv, wp, w1, w2);
    // 1. LN1 -> h (half)
    ln_kernel<<<NTOK / 8, 256>>>(x, g1, be1, h);
    // 2. QKV GEMM -> qkv (half)
    gemm_h<true, false, false, false><<<dim3(QKVC / 128, NTOK / 128), 256, GEMM_SMEM>>>(
        h, wqkv, nullptr, nullptr, qkv, CDIM, QKVC);
    // 3. flash attention -> attn (half)
    attn_mma<<<dim3(2, TLEN * NHEAD), 256, ATT_SMEM>>>(qkv, attn);
    // 4. proj + bias + residual(x) -> xmid (fp32)
    gemm_h<false, true, false, true><<<dim3(CDIM / 128, NTOK / 128), 256, GEMM_SMEM>>>(
        attn, wp, bp, x, xmid, CDIM, CDIM);
    // 5. LN2 -> h (half)
    ln_kernel<<<NTOK / 8, 256>>>(xmid, g2, be2, h);
    // 6. FF1 + bias + relu -> ff (half)
    gemm_h<true, true, true, false><<<dim3(FDIM / 128, NTOK / 128), 256, GEMM_SMEM>>>(
        h, w1, b1, nullptr, ff, CDIM, FDIM);
    // 7. FF2 + bias + residual(xmid) -> out (fp32)
    gemm_h<false, true, false, true><<<dim3(CDIM / 128, NTOK / 128), 256, GEMM_SMEM>>>(
        ff, w2, b2, xmid, out, FDIM, CDIM);
}